// round 14
// baseline (speedup 1.0000x reference)
#include <cuda_runtime.h>

#define BB 256
#define TT 512
#define DD 50
#define HH 128
#define G4 512
#define HID 256

typedef unsigned long long ull;

// ---- device scratch ----
__device__ float g_xgT[2][TT][G4][BB];   // input-gate preactivations [d][t][row][b]

__device__ __forceinline__ float sigf(float x)   { return 1.0f / (1.0f + __expf(-x)); }
__device__ __forceinline__ float tanhf_(float x) { return 2.0f / (1.0f + __expf(-2.0f * x)) - 1.0f; }

__device__ __forceinline__ ull pack2(float a, float b) {
    ull r; asm("mov.b64 %0,{%1,%2};" : "=l"(r) : "f"(a), "f"(b)); return r;
}
__device__ __forceinline__ void unpack2(ull v, float& a, float& b) {
    asm("mov.b64 {%0,%1},%2;" : "=f"(a), "=f"(b) : "l"(v));
}
__device__ __forceinline__ void fma2(ull a, ull b, ull& c) {
    asm("fma.rn.f32x2 %0,%1,%2,%0;" : "+l"(c) : "l"(a), "l"(b));
}
__device__ __forceinline__ ull add2(ull a, ull b) {
    ull r; asm("add.rn.f32x2 %0,%1,%2;" : "=l"(r) : "l"(a), "l"(b)); return r;
}
__device__ __forceinline__ unsigned smem_u32(const void* p) {
    unsigned r;
    asm("{ .reg .u64 t; cvta.to.shared.u64 t, %1; cvt.u32.u64 %0, t; }" : "=r"(r) : "l"(p));
    return r;
}

// ---------------------------------------------------------------------------
// Embedding lookup + input-gate GEMM -> transposed xg (unchanged)
// ---------------------------------------------------------------------------
__global__ void __launch_bounds__(256) embed_gemm(
    const int*   __restrict__ idx,
    const float* __restrict__ emb,
    const float* __restrict__ Wih_f, const float* __restrict__ bih_f, const float* __restrict__ bhh_f,
    const float* __restrict__ Wih_b, const float* __restrict__ bih_b, const float* __restrict__ bhh_b)
{
    __shared__ __align__(16) float xsA[16 * DD * 2];
    const int tid = threadIdx.x;
    const int b0  = blockIdx.x * 32;
    const int t   = blockIdx.y;

    for (int i = tid; i < 32 * DD; i += 256) {
        int b = i / DD, k = i - b * DD;
        int id = idx[(b0 + b) * TT + t];
        xsA[(b >> 1) * (2 * DD) + k * 2 + (b & 1)] = emb[id * DD + k];
    }
    __syncthreads();

    #pragma unroll 1
    for (int g = 0; g < 4; ++g) {
        int col = tid + g * 256;
        int dir = col >> 9;
        int n   = col & 511;
        const float* W = dir ? Wih_b : Wih_f;
        float bias = dir ? (bih_b[n] + bhh_b[n]) : (bih_f[n] + bhh_f[n]);

        float w[DD];
        #pragma unroll
        for (int k = 0; k < DD; ++k) w[k] = W[n * DD + k];

        ull acc[16];
        ull bp2 = pack2(bias, bias);
        #pragma unroll
        for (int p = 0; p < 16; ++p) acc[p] = bp2;

        #pragma unroll 2
        for (int k = 0; k < DD; ++k) {
            ull w2 = pack2(w[k], w[k]);
            #pragma unroll
            for (int p = 0; p < 16; ++p) {
                ull x = *(const ull*)&xsA[p * (2 * DD) + k * 2];
                fma2(x, w2, acc[p]);
            }
        }

        float* dst = &g_xgT[dir][t][n][b0];
        #pragma unroll
        for (int p = 0; p < 16; ++p) {
            float a, b; unpack2(acc[p], a, b);
            *(float2*)&dst[2 * p] = make_float2(a, b);
        }
    }
}

// ---------------------------------------------------------------------------
// Persistent LSTM: BOTH directions per CTA (deterministic latency overlap).
// grid (4 kq, 32 bt) = 128 CTAs x 256 threads, cluster (4,1,1), 1 CTA/SM.
// Per step: phase-f (MAC->reduce->update->push), phase-b, ONE cluster barrier.
// f's shfl/MUFU tails overlap b's independent FFMA2 stream in-warp.
// All mechanics (q-permuted h layout, narrowing butterfly, 4B DSMEM pushes)
// identical to the verified R12 kernel, instantiated per direction.
// ---------------------------------------------------------------------------
#define SEC_W  132                 // words per 16-k section (16*8 + 4 pad)
#define HB_W   (8 * SEC_W)         // 1056 words per buffer

__global__ void __launch_bounds__(256, 1) __cluster_dims__(4, 1, 1)
lstm_dual(const float* __restrict__ Whh_f, const float* __restrict__ Whh_b,
          const float* __restrict__ masks, float* __restrict__ out)
{
    __shared__ __align__(16) float hb[2][2][HB_W];   // [dir][parity][..]

    const int tid  = threadIdx.x;
    const int kq   = blockIdx.x;             // k-quarter == cluster rank
    const int bt   = blockIdx.y;
    const int K0   = kq * 32;
    const int bb0  = bt * 8;
    const int lane = tid & 31;
    const int warp = tid >> 5;

    const int kkl   = lane & 3;
    const int kgrp  = lane >> 2;             // 0..7
    const int kk    = warp * 4 + kkl;        // 0..31
    const int kglob = K0 + kk;
    const int bu    = bb0 + kgrp;            // owned batch

    const float* Ws[2] = { Whh_f, Whh_b };

    // ---- weights: both dirs x 4 gate rows x own 16-k slice, in registers ----
    float w[2][4][16];
    #pragma unroll
    for (int dd = 0; dd < 2; ++dd) {
        #pragma unroll
        for (int g = 0; g < 4; ++g) {
            const float4* src = (const float4*)&Ws[dd][(g * 128 + kglob) * 128 + kgrp * 16];
            #pragma unroll
            for (int q = 0; q < 4; ++q) {
                float4 v = src[q];
                w[dd][g][4 * q + 0] = v.x; w[dd][g][4 * q + 1] = v.y;
                w[dd][g][4 * q + 2] = v.z; w[dd][g][4 * q + 3] = v.w;
            }
        }
    }

    // zero parity-0 buffers of both dirs
    for (int i = tid; i < HB_W; i += 256) { hb[0][0][i] = 0.f; hb[1][0][i] = 0.f; }

    // ---- h store word (q-permuted, as in R12) + peer push base addresses ----
    const int hs  = kglob >> 4;
    const int hq  = ((kgrp >> 1) ^ (hs >> 1)) & 3;
    const int hw  = hs * SEC_W + (kglob & 15) * 8 + hq * 2 + (kgrp & 1);
    // byte offset of hb[dd][par] from hb[0][0]:
    //   (dd*2 + par) * HB_W * 4
    unsigned rbase[3];
    {
        unsigned a0 = smem_u32(&hb[0][0][0]) + (unsigned)(hw * 4);
        #pragma unroll
        for (int p = 0; p < 3; ++p) {
            unsigned pr = (kq + 1 + p) & 3;
            asm("mapa.shared::cluster.u32 %0, %1, %2;" : "=r"(rbase[p]) : "r"(a0), "r"(pr));
        }
    }
    char* lbase = (char*)&hb[0][0][0] + hw * 4;

    // ---- per-thread state (both dirs) ----
    float c[2] = { 0.f, 0.f };
    float m[2] = { -3.0e38f, -3.0e38f };

    // prefetch xg + mask penalty for step 0, both dirs
    float xn[2][4], pen[2];
    #pragma unroll
    for (int dd = 0; dd < 2; ++dd) {
        int t0 = dd ? (TT - 1) : 0;
        const float* p = &g_xgT[dd][t0][0][bu];
        xn[dd][0] = __ldg(p + (0 * 128 + kglob) * BB);
        xn[dd][1] = __ldg(p + (1 * 128 + kglob) * BB);
        xn[dd][2] = __ldg(p + (2 * 128 + kglob) * BB);
        xn[dd][3] = __ldg(p + (3 * 128 + kglob) * BB);
        pen[dd] = (1.0f - __ldg(&masks[bu * TT + t0])) * 1e8f;
    }

    __syncthreads();   // local parity-0 buffers zeroed

    const int hie = kgrp & 1;

    int cur = 0;
    for (int s = 0; s < TT; ++s) {
        #pragma unroll
        for (int dd = 0; dd < 2; ++dd) {
            float cx0 = xn[dd][0], cx1 = xn[dd][1], cx2 = xn[dd][2], cx3 = xn[dd][3];
            float cpen = pen[dd];
            // prefetch next step (hides under MAC loop)
            {
                int t2 = dd ? (TT - 2 - s) : (s + 1);
                t2 = (t2 < 0) ? 0 : (t2 > TT - 1 ? TT - 1 : t2);
                const float* p = &g_xgT[dd][t2][0][bu];
                xn[dd][0] = __ldg(p + (0 * 128 + kglob) * BB);
                xn[dd][1] = __ldg(p + (1 * 128 + kglob) * BB);
                xn[dd][2] = __ldg(p + (2 * 128 + kglob) * BB);
                xn[dd][3] = __ldg(p + (3 * 128 + kglob) * BB);
                pen[dd] = (1.0f - __ldg(&masks[bu * TT + t2])) * 1e8f;
            }

            // ---- MAC: own 16-k slice, 4 gates x 4 q-slots ----
            ull A[4][4];
            #pragma unroll
            for (int g = 0; g < 4; ++g)
                #pragma unroll
                for (int q = 0; q < 4; ++q) A[g][q] = 0ull;

            const float* hc = &hb[dd][cur][kgrp * SEC_W];
            #pragma unroll
            for (int i = 0; i < 16; ++i) {
                ulonglong2 hA = *(const ulonglong2*)(hc + i * 8);      // q=0,1
                ulonglong2 hB = *(const ulonglong2*)(hc + i * 8 + 4);  // q=2,3
                #pragma unroll
                for (int g = 0; g < 4; ++g) {
                    ull w2 = pack2(w[dd][g][i], w[dd][g][i]);
                    fma2(hA.x, w2, A[g][0]);
                    fma2(hA.y, w2, A[g][1]);
                    fma2(hB.x, w2, A[g][2]);
                    fma2(hB.y, w2, A[g][3]);
                }
            }

            // ---- narrowing butterfly over 8 kgrps ----
            #pragma unroll
            for (int g = 0; g < 4; ++g) {
                A[g][0] = add2(A[g][0], __shfl_xor_sync(0xffffffffu, A[g][2], 16));
                A[g][1] = add2(A[g][1], __shfl_xor_sync(0xffffffffu, A[g][3], 16));
            }
            #pragma unroll
            for (int g = 0; g < 4; ++g)
                A[g][0] = add2(A[g][0], __shfl_xor_sync(0xffffffffu, A[g][1], 8));
            #pragma unroll
            for (int g = 0; g < 4; ++g)
                A[g][0] = add2(A[g][0], __shfl_xor_sync(0xffffffffu, A[g][0], 4));

            // ---- update: lane owns (kglob, bu, dir dd) ----
            float aa, bb2, gi, gf, gg, go;
            unpack2(A[0][0], aa, bb2); gi = hie ? bb2 : aa;
            unpack2(A[1][0], aa, bb2); gf = hie ? bb2 : aa;
            unpack2(A[2][0], aa, bb2); gg = hie ? bb2 : aa;
            unpack2(A[3][0], aa, bb2); go = hie ? bb2 : aa;
            gi += cx0; gf += cx1; gg += cx2; go += cx3;

            c[dd] = sigf(gf) * c[dd] + sigf(gi) * tanhf_(gg);
            float hv = sigf(go) * tanhf_(c[dd]);
            m[dd] = fmaxf(m[dd], hv - cpen);

            if (s < TT - 1) {
                // write next h buffer: local + 3 DSMEM peers (4B each)
                unsigned boff = (unsigned)(((dd * 2) + (cur ^ 1)) * HB_W * 4);
                *(float*)(lbase + boff) = hv;
                asm volatile("st.shared::cluster.f32 [%0], %1;"
                             :: "r"(rbase[0] + boff), "f"(hv) : "memory");
                asm volatile("st.shared::cluster.f32 [%0], %1;"
                             :: "r"(rbase[1] + boff), "f"(hv) : "memory");
                asm volatile("st.shared::cluster.f32 [%0], %1;"
                             :: "r"(rbase[2] + boff), "f"(hv) : "memory");
            }
        }

        if (s < TT - 1) {
            // ONE split cluster barrier per step: orders both dirs' pushes
            asm volatile("barrier.cluster.arrive.aligned;" ::: "memory");
            asm volatile("barrier.cluster.wait.aligned;"   ::: "memory");
        }

        cur ^= 1;
    }

    out[bu * HID + 0 * HH + kglob] = m[0];
    out[bu * HID + 1 * HH + kglob] = m[1];
}

// ---------------------------------------------------------------------------
extern "C" void kernel_launch(void* const* d_in, const int* in_sizes, int n_in,
                              void* d_out, int out_size)
{
    (void)in_sizes; (void)n_in; (void)out_size;
    const int*   idx   = (const int*)  d_in[0];
    const float* masks = (const float*)d_in[1];
    const float* emb   = (const float*)d_in[2];
    const float* Wih_f = (const float*)d_in[3];
    const float* Whh_f = (const float*)d_in[4];
    const float* bih_f = (const float*)d_in[5];
    const float* bhh_f = (const float*)d_in[6];
    const float* Wih_b = (const float*)d_in[7];
    const float* Whh_b = (const float*)d_in[8];
    const float* bih_b = (const float*)d_in[9];
    const float* bhh_b = (const float*)d_in[10];
    float* out = (float*)d_out;

    embed_gemm<<<dim3(8, TT), 256>>>(idx, emb, Wih_f, bih_f, bhh_f,
                                     Wih_b, bih_b, bhh_b);
    lstm_dual<<<dim3(4, 32), 256>>>(Whh_f, Whh_b, masks, out);
}

// round 15
// speedup vs baseline: 1.0719x; 1.0719x over previous
#include <cuda_runtime.h>

#define BB 256
#define TT 512
#define DD 50
#define HH 128
#define G4 512
#define HID 256

typedef unsigned long long ull;

// ---- device scratch ----
__device__ float g_xgT[2][TT][G4][BB];   // input-gate preactivations [d][t][row][b]

__device__ __forceinline__ float sigf(float x)   { return 1.0f / (1.0f + __expf(-x)); }
__device__ __forceinline__ float tanhf_(float x) { return 2.0f / (1.0f + __expf(-2.0f * x)) - 1.0f; }

__device__ __forceinline__ ull pack2(float a, float b) {
    ull r; asm("mov.b64 %0,{%1,%2};" : "=l"(r) : "f"(a), "f"(b)); return r;
}
__device__ __forceinline__ void unpack2(ull v, float& a, float& b) {
    asm("mov.b64 {%0,%1},%2;" : "=f"(a), "=f"(b) : "l"(v));
}
__device__ __forceinline__ void fma2(ull a, ull b, ull& c) {
    asm("fma.rn.f32x2 %0,%1,%2,%0;" : "+l"(c) : "l"(a), "l"(b));
}
__device__ __forceinline__ ull add2(ull a, ull b) {
    ull r; asm("add.rn.f32x2 %0,%1,%2;" : "=l"(r) : "l"(a), "l"(b)); return r;
}
__device__ __forceinline__ unsigned smem_u32(const void* p) {
    unsigned r;
    asm("{ .reg .u64 t; cvta.to.shared.u64 t, %1; cvt.u32.u64 %0, t; }" : "=r"(r) : "l"(p));
    return r;
}

// ---------------------------------------------------------------------------
// Embedding lookup + input-gate GEMM -> transposed xg (unchanged)
// ---------------------------------------------------------------------------
__global__ void __launch_bounds__(256) embed_gemm(
    const int*   __restrict__ idx,
    const float* __restrict__ emb,
    const float* __restrict__ Wih_f, const float* __restrict__ bih_f, const float* __restrict__ bhh_f,
    const float* __restrict__ Wih_b, const float* __restrict__ bih_b, const float* __restrict__ bhh_b)
{
    __shared__ __align__(16) float xsA[16 * DD * 2];
    const int tid = threadIdx.x;
    const int b0  = blockIdx.x * 32;
    const int t   = blockIdx.y;

    for (int i = tid; i < 32 * DD; i += 256) {
        int b = i / DD, k = i - b * DD;
        int id = idx[(b0 + b) * TT + t];
        xsA[(b >> 1) * (2 * DD) + k * 2 + (b & 1)] = emb[id * DD + k];
    }
    __syncthreads();

    #pragma unroll 1
    for (int g = 0; g < 4; ++g) {
        int col = tid + g * 256;
        int dir = col >> 9;
        int n   = col & 511;
        const float* W = dir ? Wih_b : Wih_f;
        float bias = dir ? (bih_b[n] + bhh_b[n]) : (bih_f[n] + bhh_f[n]);

        float w[DD];
        #pragma unroll
        for (int k = 0; k < DD; ++k) w[k] = W[n * DD + k];

        ull acc[16];
        ull bp2 = pack2(bias, bias);
        #pragma unroll
        for (int p = 0; p < 16; ++p) acc[p] = bp2;

        #pragma unroll 2
        for (int k = 0; k < DD; ++k) {
            ull w2 = pack2(w[k], w[k]);
            #pragma unroll
            for (int p = 0; p < 16; ++p) {
                ull x = *(const ull*)&xsA[p * (2 * DD) + k * 2];
                fma2(x, w2, acc[p]);
            }
        }

        float* dst = &g_xgT[dir][t][n][b0];
        #pragma unroll
        for (int p = 0; p < 16; ++p) {
            float a, b; unpack2(acc[p], a, b);
            *(float2*)&dst[2 * p] = make_float2(a, b);
        }
    }
}

// ---------------------------------------------------------------------------
// Persistent LSTM recurrence: 2-CTA clusters, 512-thread CTAs, 1 CTA/SM.
// grid (2 kq, 32 bt, 2 dir) = 128 CTAs; 128 independent clusters -> no
// cross-cluster jitter coupling. Inner machinery identical to R12:
// thread (kk = warp*4+kkl [0..63], kgrp = lane>>2) owns all 4 gates of its
// k-output over a 16-k input slice; q-permuted h layout; narrowing butterfly.
// Split cluster barrier: arrive after pushes, wait after next prefetch.
// ---------------------------------------------------------------------------
#define SEC_W  132                 // words per 16-k section (16*8 + 4 pad)
#define HB_W   (8 * SEC_W)         // 1056 words per buffer

__global__ void __launch_bounds__(512, 1) __cluster_dims__(2, 1, 1)
lstm_pairq(const float* __restrict__ Whh_f, const float* __restrict__ Whh_b,
           const float* __restrict__ masks, float* __restrict__ out)
{
    __shared__ __align__(16) float hb[2][HB_W];

    const int tid  = threadIdx.x;
    const int kq   = blockIdx.x;             // k-half == cluster rank
    const int bt   = blockIdx.y;
    const int d    = blockIdx.z;
    const int K0   = kq * 64;
    const int bb0  = bt * 8;
    const int lane = tid & 31;
    const int warp = tid >> 5;               // 0..15

    const int kkl   = lane & 3;
    const int kgrp  = lane >> 2;             // 0..7 (lane bits 2..4 -> xor 4,8,16)
    const int kk    = warp * 4 + kkl;        // 0..63
    const int kglob = K0 + kk;               // 0..127
    const int bu    = bb0 + kgrp;            // owned batch

    const float* Whh = d ? Whh_b : Whh_f;

    // ---- weights: 4 gate rows x own 16-k slice, in registers ----
    float w[4][16];
    #pragma unroll
    for (int g = 0; g < 4; ++g) {
        const float4* src = (const float4*)&Whh[(g * 128 + kglob) * 128 + kgrp * 16];
        #pragma unroll
        for (int q = 0; q < 4; ++q) {
            float4 v = src[q];
            w[g][4 * q + 0] = v.x; w[g][4 * q + 1] = v.y;
            w[g][4 * q + 2] = v.z; w[g][4 * q + 3] = v.w;
        }
    }

    // zero h buffer 0
    for (int i = tid; i < HB_W; i += 512) hb[0][i] = 0.f;

    // ---- h store word (q-permuted, as in R12) + peer push address ----
    const int hs  = kglob >> 4;                       // 0..7
    const int hq  = ((kgrp >> 1) ^ (hs >> 1)) & 3;
    const int hw  = hs * SEC_W + (kglob & 15) * 8 + hq * 2 + (kgrp & 1);
    char* lbase = (char*)&hb[0][0] + hw * 4;
    const unsigned par_off = (unsigned)(HB_W * 4);    // hb[1] - hb[0] bytes
    unsigned rpeer;
    {
        unsigned a0 = smem_u32(&hb[0][0]) + (unsigned)(hw * 4);
        unsigned pr = kq ^ 1;
        asm("mapa.shared::cluster.u32 %0, %1, %2;" : "=r"(rpeer) : "r"(a0), "r"(pr));
    }

    // ---- per-thread state ----
    float c = 0.f, m = -3.0e38f;

    const int tstep = d ? -1 : 1;
    int t = d ? (TT - 1) : 0;

    // prefetch xg (4 gate rows, own batch) + mask penalty for step 0
    float xn0, xn1, xn2, xn3, pen;
    {
        const float* p = &g_xgT[d][t][0][bu];
        xn0 = __ldg(p + (0 * 128 + kglob) * BB);
        xn1 = __ldg(p + (1 * 128 + kglob) * BB);
        xn2 = __ldg(p + (2 * 128 + kglob) * BB);
        xn3 = __ldg(p + (3 * 128 + kglob) * BB);
        pen = (1.0f - __ldg(&masks[bu * TT + t])) * 1e8f;
    }

    __syncthreads();   // hb[0] zeroed (local); peer independent

    const int hie = kgrp & 1;

    int cur = 0;
    for (int s = 0; s < TT; ++s) {
        float cx0 = xn0, cx1 = xn1, cx2 = xn2, cx3 = xn3, cpen = pen;
        // prefetch next step (issues before the barrier wait below)
        {
            int t2 = t + tstep;
            t2 = (t2 < 0) ? 0 : (t2 > TT - 1 ? TT - 1 : t2);
            const float* p = &g_xgT[d][t2][0][bu];
            xn0 = __ldg(p + (0 * 128 + kglob) * BB);
            xn1 = __ldg(p + (1 * 128 + kglob) * BB);
            xn2 = __ldg(p + (2 * 128 + kglob) * BB);
            xn3 = __ldg(p + (3 * 128 + kglob) * BB);
            pen = (1.0f - __ldg(&masks[bu * TT + t2])) * 1e8f;
        }

        // complete last step's h exchange (arrive happened after the pushes)
        if (s > 0) {
            asm volatile("barrier.cluster.wait.aligned;" ::: "memory");
        }

        // ---- MAC: own 16-k slice, 4 gates x 4 q-slots (q-permuted pairs) ----
        ull A[4][4];
        #pragma unroll
        for (int g = 0; g < 4; ++g)
            #pragma unroll
            for (int q = 0; q < 4; ++q) A[g][q] = 0ull;

        const float* hc = &hb[cur][kgrp * SEC_W];
        #pragma unroll
        for (int i = 0; i < 16; ++i) {
            ulonglong2 hA = *(const ulonglong2*)(hc + i * 8);      // q=0, q=1
            ulonglong2 hB = *(const ulonglong2*)(hc + i * 8 + 4);  // q=2, q=3
            #pragma unroll
            for (int g = 0; g < 4; ++g) {
                ull w2 = pack2(w[g][i], w[g][i]);
                fma2(hA.x, w2, A[g][0]);
                fma2(hA.y, w2, A[g][1]);
                fma2(hB.x, w2, A[g][2]);
                fma2(hB.y, w2, A[g][3]);
            }
        }

        // ---- narrowing butterfly over 8 kgrps (32 SHFL + 16 add2) ----
        #pragma unroll
        for (int g = 0; g < 4; ++g) {
            A[g][0] = add2(A[g][0], __shfl_xor_sync(0xffffffffu, A[g][2], 16));
            A[g][1] = add2(A[g][1], __shfl_xor_sync(0xffffffffu, A[g][3], 16));
        }
        #pragma unroll
        for (int g = 0; g < 4; ++g)
            A[g][0] = add2(A[g][0], __shfl_xor_sync(0xffffffffu, A[g][1], 8));
        #pragma unroll
        for (int g = 0; g < 4; ++g)
            A[g][0] = add2(A[g][0], __shfl_xor_sync(0xffffffffu, A[g][0], 4));

        // ---- update: lane owns (kglob, bu); pick hie half of A[g][0] ----
        float aa, bb2, gi, gf, gg, go;
        unpack2(A[0][0], aa, bb2); gi = hie ? bb2 : aa;
        unpack2(A[1][0], aa, bb2); gf = hie ? bb2 : aa;
        unpack2(A[2][0], aa, bb2); gg = hie ? bb2 : aa;
        unpack2(A[3][0], aa, bb2); go = hie ? bb2 : aa;
        gi += cx0; gf += cx1; gg += cx2; go += cx3;

        c = sigf(gf) * c + sigf(gi) * tanhf_(gg);
        float hv = sigf(go) * tanhf_(c);
        m = fmaxf(m, hv - cpen);

        if (s < TT - 1) {
            // write next h buffer: local + 1 DSMEM peer (4B each)
            unsigned nb = cur ? 0u : par_off;
            *(float*)(lbase + nb) = hv;
            asm volatile("st.shared::cluster.f32 [%0], %1;"
                         :: "r"(rpeer + nb), "f"(hv) : "memory");
            // release our pushes; wait happens after next step's prefetch
            asm volatile("barrier.cluster.arrive.aligned;" ::: "memory");
        }

        cur ^= 1;
        t += tstep;
    }

    out[bu * HID + d * HH + kglob] = m;
}

// ---------------------------------------------------------------------------
extern "C" void kernel_launch(void* const* d_in, const int* in_sizes, int n_in,
                              void* d_out, int out_size)
{
    (void)in_sizes; (void)n_in; (void)out_size;
    const int*   idx   = (const int*)  d_in[0];
    const float* masks = (const float*)d_in[1];
    const float* emb   = (const float*)d_in[2];
    const float* Wih_f = (const float*)d_in[3];
    const float* Whh_f = (const float*)d_in[4];
    const float* bih_f = (const float*)d_in[5];
    const float* bhh_f = (const float*)d_in[6];
    const float* Wih_b = (const float*)d_in[7];
    const float* Whh_b = (const float*)d_in[8];
    const float* bih_b = (const float*)d_in[9];
    const float* bhh_b = (const float*)d_in[10];
    float* out = (float*)d_out;

    embed_gemm<<<dim3(8, TT), 256>>>(idx, emb, Wih_f, bih_f, bhh_f,
                                     Wih_b, bih_b, bhh_b);
    lstm_pairq<<<dim3(2, 32, 2), 512>>>(Whh_f, Whh_b, masks, out);
}